// round 15
// baseline (speedup 1.0000x reference)
#include <cuda_runtime.h>
#include <cuda_fp16.h>
#include <math.h>
#include <stdint.h>

#define DIMC 768
#define NH 8
#define HD 96
#define BATCH 4
#define SEQ 2048
#define MTOT (BATCH*SEQ)

// Scratch (static device arrays; no cudaMalloc allowed)
__device__ float g_q[(size_t)BATCH*NH*SEQ*HD];
__device__ float g_k[(size_t)BATCH*NH*SEQ*HD];
__device__ __half g_kh[(size_t)BATCH*NH*SEQ*HD];    // K after rope, fp16 [b,h,t,d]
__device__ __half g_vth[(size_t)BATCH*NH*HD*SEQ];   // V transposed fp16 [b,h,d,t]
__device__ __half g_atth[(size_t)MTOT*DIMC];        // attention out, fp16
__device__ __half g_xh[(size_t)MTOT*DIMC];          // x, fp16
__device__ __half g_wqh[(size_t)3*DIMC*DIMC];       // w_qkv, fp16
__device__ __half g_wph[(size_t)DIMC*DIMC];         // w_proj, fp16

// ---------------------------------------------------------------------------
// helpers
// ---------------------------------------------------------------------------
__device__ __forceinline__ uint32_t smem_u32(const void* p) {
    uint32_t a;
    asm("{ .reg .u64 t; cvta.to.shared.u64 t, %1; cvt.u32.u64 %0, t; }" : "=r"(a) : "l"(p));
    return a;
}
__device__ __forceinline__ void cp16(uint32_t s, const void* g) {
    asm volatile("cp.async.ca.shared.global [%0], [%1], 16;" :: "r"(s), "l"(g) : "memory");
}
__device__ __forceinline__ void cp_commit() {
    asm volatile("cp.async.commit_group;" ::: "memory");
}
__device__ __forceinline__ void cp_wait1() {
    asm volatile("cp.async.wait_group 1;" ::: "memory");
}
// pack two f32 -> f16x2 (x0 -> low half)
__device__ __forceinline__ uint32_t packh2(float x0, float x1) {
    uint32_t r;
    asm("cvt.rn.f16x2.f32 %0, %1, %2;" : "=r"(r) : "f"(x1), "f"(x0));
    return r;
}
__device__ __forceinline__ void ldsm4(uint32_t& r0, uint32_t& r1, uint32_t& r2,
                                      uint32_t& r3, uint32_t addr) {
    asm volatile("ldmatrix.sync.aligned.m8n8.x4.shared.b16 {%0,%1,%2,%3}, [%4];"
                 : "=r"(r0), "=r"(r1), "=r"(r2), "=r"(r3) : "r"(addr));
}
// fp16 inputs, f32 accum, k16
__device__ __forceinline__ void mma_h(float d[4], uint32_t a0, uint32_t a1,
                                      uint32_t a2, uint32_t a3,
                                      uint32_t b0, uint32_t b1) {
    asm volatile(
        "mma.sync.aligned.m16n8k16.row.col.f32.f16.f16.f32 "
        "{%0,%1,%2,%3},{%4,%5,%6,%7},{%8,%9},{%0,%1,%2,%3};"
        : "+f"(d[0]), "+f"(d[1]), "+f"(d[2]), "+f"(d[3])
        : "r"(a0), "r"(a1), "r"(a2), "r"(a3), "r"(b0), "r"(b1));
}

// ---------------------------------------------------------------------------
// pack: f32 -> fp16 (8 floats per thread)
// ---------------------------------------------------------------------------
__global__ __launch_bounds__(256)
void pack_h_kernel(const float* __restrict__ src, __half* __restrict__ dst, int n8)
{
    int i = blockIdx.x * blockDim.x + threadIdx.x;
    if (i < n8) {
        float4 v0 = ((const float4*)src)[2*i];
        float4 v1 = ((const float4*)src)[2*i+1];
        uint4 o;
        o.x = packh2(v0.x, v0.y);
        o.y = packh2(v0.z, v0.w);
        o.z = packh2(v1.x, v1.y);
        o.w = packh2(v1.z, v1.w);
        ((uint4*)dst)[i] = o;
    }
}

// ---------------------------------------------------------------------------
// GEMM (R14 winner): fp16 mma, 512 threads, CTA tile 128 x BN, warp grid
// WM x WN, k-chunk 32, 3-stage cp.async ring.
// MODE 0: scatter q/k -> f32, v -> g_vth fp16 transposed. MODE 1: write Cout.
// ---------------------------------------------------------------------------
#define KCH 40   // half stride per row (80B, odd multiple of 16B)

template<int MODE, int BN, int WM, int WN>
__global__ __launch_bounds__(512, 1)
void gemm_h(const __half* __restrict__ A, const __half* __restrict__ W,
            const float* __restrict__ bias, float* __restrict__ Cout)
{
    constexpr int ASZ = 128 * KCH;
    constexpr int WSZ = BN * KCH;
    constexpr int STG = ASZ + WSZ;
    constexpr int MT  = 128 / (WM * 16);
    constexpr int NT  = BN / (WN * 8);
    constexpr int NBK = NT / 2;
    constexpr int NIT = (128 + BN) * 4 / 512;

    extern __shared__ __half smh[];
    uint32_t smb = smem_u32(smh);

    int tid = threadIdx.x;
    int lane = tid & 31;
    int wid = tid >> 5;
    int g = lane >> 2, j = lane & 3;
    int wm = wid % WM, wn = wid / WM;
    int m0 = blockIdx.y * 128;
    int n0 = blockIdx.x * BN;

    auto issue = [&](int c) {
        uint32_t stb = smb + (uint32_t)((c % 3) * STG) * 2;
#pragma unroll
        for (int it = 0; it < NIT; it++) {
            int f = tid + it * 512;
            int row = f >> 2;
            int ch = (f & 3) * 8;
            if (row < 128) {
                cp16(stb + (uint32_t)(row * KCH + ch) * 2,
                     A + (size_t)(m0 + row) * DIMC + c * 32 + ch);
            } else {
                int wrow = row - 128;
                cp16(stb + (uint32_t)(ASZ + wrow * KCH + ch) * 2,
                     W + (size_t)(n0 + wrow) * DIMC + c * 32 + ch);
            }
        }
    };

    int aRowB = wm * (MT * 16) + (lane & 7) + ((lane >> 3) & 1) * 8;
    int aCol  = ((lane >> 4) & 1) * 8;
    int bRowB = wn * (NT * 8) + (lane & 7) + ((lane >> 4) & 1) * 8;
    int bCol  = ((lane >> 3) & 1) * 8;

    float Cf[MT][NT][4];
#pragma unroll
    for (int mt = 0; mt < MT; mt++)
#pragma unroll
        for (int nt = 0; nt < NT; nt++)
#pragma unroll
            for (int r = 0; r < 4; r++) Cf[mt][nt][r] = 0.f;

    issue(0); cp_commit();
    issue(1); cp_commit();

    const int NC = DIMC / 32;
    for (int c = 0; c < NC; c++) {
        cp_wait1();
        __syncthreads();
        if (c + 2 < NC) issue(c + 2);
        cp_commit();

        uint32_t stA = smb + (uint32_t)((c % 3) * STG) * 2;
        uint32_t stW = stA + (uint32_t)ASZ * 2;

#pragma unroll
        for (int ks = 0; ks < 2; ks++) {
            uint32_t a[MT][4], b[NT][2];
#pragma unroll
            for (int mt = 0; mt < MT; mt++)
                ldsm4(a[mt][0], a[mt][1], a[mt][2], a[mt][3],
                      stA + (uint32_t)((aRowB + mt * 16) * KCH + ks * 16 + aCol) * 2);
#pragma unroll
            for (int bk = 0; bk < NBK; bk++)
                ldsm4(b[2*bk][0], b[2*bk][1], b[2*bk+1][0], b[2*bk+1][1],
                      stW + (uint32_t)((bRowB + bk * 16) * KCH + ks * 16 + bCol) * 2);
#pragma unroll
            for (int mt = 0; mt < MT; mt++)
#pragma unroll
                for (int nt = 0; nt < NT; nt++)
                    mma_h(Cf[mt][nt], a[mt][0], a[mt][1], a[mt][2], a[mt][3],
                          b[nt][0], b[nt][1]);
        }
    }

    // epilogue
#pragma unroll
    for (int mt = 0; mt < MT; mt++) {
        int row0 = m0 + wm * (MT * 16) + mt * 16 + g;
#pragma unroll
        for (int nt = 0; nt < NT; nt++) {
            int col = n0 + wn * (NT * 8) + nt * 8 + 2 * j;
            float b0 = bias[col], b1 = bias[col + 1];
            float2 v0 = make_float2(Cf[mt][nt][0] + b0, Cf[mt][nt][1] + b1);
            float2 v1 = make_float2(Cf[mt][nt][2] + b0, Cf[mt][nt][3] + b1);
            if (MODE == 1) {
                *(float2*)(Cout + (size_t)row0 * DIMC + col) = v0;
                *(float2*)(Cout + (size_t)(row0 + 8) * DIMC + col) = v1;
            } else {
                int s = (col >= 2 * DIMC) ? 2 : (col >= DIMC ? 1 : 0);
                int rr = col - s * DIMC;
                int hh = rr / HD;
                int d = rr - hh * HD;
                int bb0 = row0 >> 11, t0 = row0 & (SEQ - 1);
                int r1 = row0 + 8;
                int bb1 = r1 >> 11, t1 = r1 & (SEQ - 1);
                if (s == 2) {
                    __half* dv0 = g_vth + ((size_t)(bb0 * NH + hh) * HD + d) * SEQ + t0;
                    dv0[0] = __float2half_rn(v0.x); dv0[SEQ] = __float2half_rn(v0.y);
                    __half* dv1 = g_vth + ((size_t)(bb1 * NH + hh) * HD + d) * SEQ + t1;
                    dv1[0] = __float2half_rn(v1.x); dv1[SEQ] = __float2half_rn(v1.y);
                } else {
                    float* base = (s == 0) ? g_q : g_k;
                    *(float2*)(base + ((size_t)(bb0 * NH + hh) * SEQ + t0) * HD + d) = v0;
                    *(float2*)(base + ((size_t)(bb1 * NH + hh) * SEQ + t1) * HD + d) = v1;
                }
            }
        }
    }
}

#define GEMM_SMEM_256 (3*(128+256)*KCH*2)
#define GEMM_SMEM_128 (3*(128+128)*KCH*2)

// ---------------------------------------------------------------------------
// RoPE: q in place (f32), k -> g_kh (fp16).
// ---------------------------------------------------------------------------
__global__ __launch_bounds__(256)
void rope_kernel()
{
    int idx = blockIdx.x * blockDim.x + threadIdx.x;
    int j = idx % 48;
    int rest = idx / 48;
    int t = rest & (SEQ - 1);
    int bh = rest >> 11;

    float freq = exp2f(-(2.f * j / 96.f) * 13.287712379549449f);
    float ang = (float)t * freq;
    float sn, cs;
    sincosf(ang, &sn, &cs);

    size_t base = ((size_t)bh * SEQ + t) * HD;
    float q1 = g_q[base + j], q2 = g_q[base + j + 48];
    g_q[base + j]      = q1 * cs - q2 * sn;
    g_q[base + j + 48] = q2 * cs + q1 * sn;
    float k1 = g_k[base + j], k2 = g_k[base + j + 48];
    g_kh[base + j]      = __float2half_rn(k1 * cs - k2 * sn);
    g_kh[base + j + 48] = __float2half_rn(k2 * cs + k1 * sn);
}

// ---------------------------------------------------------------------------
// Flash attention v8: fp16 mma, 3-stage cp.async ring (prefetch distance 2,
// wait_group 1) AND 2 CTAs/SM (16 warps). Shuffle-free P relayout.
// One __syncthreads per K-tile.
// ---------------------------------------------------------------------------
#define QLDH 104
#define KLDH 104
#define VTLDH 72
#define KVSTGH (64*KLDH + 96*VTLDH)
#define ATTN_SMEM ((128*QLDH + 3*KVSTGH) * 2)   // 108032 B; x2 CTAs = 216 KB/SM

__global__ __launch_bounds__(256, 2)
void attn_mma()
{
    extern __shared__ __half smh[];
    __half* Qh = smh;
    __half* KV = smh + 128 * QLDH;

    int qt = gridDim.x - 1 - blockIdx.x;
    int hh = blockIdx.y, b = blockIdx.z;
    int tid = threadIdx.x;
    int lane = tid & 31;
    int wid = tid >> 5;
    int g = lane >> 2, j = lane & 3;
    const float scale = rsqrtf((float)HD);

    const float* Qg = g_q + ((size_t)(b * NH + hh) * SEQ + (size_t)qt * 128) * HD;
    const __half* Kg = g_kh + ((size_t)(b * NH + hh) * SEQ) * HD;
    const __half* Vtg = g_vth + ((size_t)(b * NH + hh) * HD) * SEQ;

    int nkt = 2 * qt + 2;

    auto issue_kv = [&](int kt) {
        int st = kt % 3;
        __half* Ks = KV + st * KVSTGH;
        __half* Vs = Ks + 64 * KLDH;
        const __half* kp = Kg + (size_t)kt * 64 * HD;
#pragma unroll
        for (int it = 0; it < 3; it++) {
            int f = tid + it * 256;
            int r = f / 12, ch = f % 12;
            cp16(smem_u32(Ks + r * KLDH + ch * 8), kp + (size_t)r * HD + ch * 8);
        }
        const __half* vp = Vtg + kt * 64;
#pragma unroll
        for (int it = 0; it < 3; it++) {
            int f = tid + it * 256;
            int d = f >> 3, ch = f & 7;
            cp16(smem_u32(Vs + d * VTLDH + ch * 8), vp + (size_t)d * SEQ + ch * 8);
        }
    };

    issue_kv(0); cp_commit();
    issue_kv(1); cp_commit();

    for (int f = tid; f < 128 * 24; f += 256) {
        int r = f / 24, c4 = (f % 24) * 4;
        float4 v = *(const float4*)(Qg + (size_t)r * HD + c4);
        uint32_t h0 = packh2(v.x * scale, v.y * scale);
        uint32_t h1 = packh2(v.z * scale, v.w * scale);
        uint32_t* dst = (uint32_t*)(Qh + r * QLDH + c4);
        dst[0] = h0; dst[1] = h1;
    }

    uint32_t qsb = smem_u32(Qh);
    uint32_t kvb = smem_u32(KV);
    int qRow = wid * 16 + (lane & 7) + ((lane >> 3) & 1) * 8;
    int qCol = ((lane >> 4) & 1) * 8;
    int bRow = (lane & 7) + ((lane >> 4) & 1) * 8;
    int bCol = ((lane >> 3) & 1) * 8;

    float m0r = -1e30f, m1r = -1e30f, l0r = 0.f, l1r = 0.f;
    float O[12][4];
#pragma unroll
    for (int nt = 0; nt < 12; nt++)
#pragma unroll
        for (int r = 0; r < 4; r++) O[nt][r] = 0.f;

    int row0 = qt * 128 + wid * 16 + g;

    for (int kt = 0; kt < nkt; kt++) {
        cp_wait1();
        __syncthreads();     // stage kt visible; all reads of slot (kt-1)%3 done
        if (kt + 2 < nkt) issue_kv(kt + 2);
        cp_commit();

        uint32_t ksb = kvb + (uint32_t)((kt % 3) * KVSTGH) * 2;
        uint32_t vsb = ksb + (uint32_t)(64 * KLDH) * 2;

        float S[8][4];
#pragma unroll
        for (int nt = 0; nt < 8; nt++)
#pragma unroll
            for (int r = 0; r < 4; r++) S[nt][r] = 0.f;

#pragma unroll
        for (int ks = 0; ks < 6; ks++) {
            uint32_t a0, a1, a2, a3;
            ldsm4(a0, a1, a2, a3, qsb + (uint32_t)(qRow * QLDH + ks * 16 + qCol) * 2);
#pragma unroll
            for (int bk = 0; bk < 4; bk++) {
                uint32_t b0, b1, b2, b3;
                ldsm4(b0, b1, b2, b3,
                      ksb + (uint32_t)((bRow + bk * 16) * KLDH + ks * 16 + bCol) * 2);
                mma_h(S[2*bk],   a0, a1, a2, a3, b0, b1);
                mma_h(S[2*bk+1], a0, a1, a2, a3, b2, b3);
            }
        }

        if (kt >= nkt - 2) {
            int colb = kt * 64;
#pragma unroll
            for (int nt = 0; nt < 8; nt++) {
                int c0 = colb + nt * 8 + 2 * j;
                if (c0 > row0)     S[nt][0] = -1e30f;
                if (c0 + 1 > row0) S[nt][1] = -1e30f;
                if (c0 > row0 + 8)     S[nt][2] = -1e30f;
                if (c0 + 1 > row0 + 8) S[nt][3] = -1e30f;
            }
        }

        float mx0 = -1e30f, mx1 = -1e30f;
#pragma unroll
        for (int nt = 0; nt < 8; nt++) {
            mx0 = fmaxf(mx0, fmaxf(S[nt][0], S[nt][1]));
            mx1 = fmaxf(mx1, fmaxf(S[nt][2], S[nt][3]));
        }
        mx0 = fmaxf(mx0, __shfl_xor_sync(0xffffffffu, mx0, 1));
        mx0 = fmaxf(mx0, __shfl_xor_sync(0xffffffffu, mx0, 2));
        mx1 = fmaxf(mx1, __shfl_xor_sync(0xffffffffu, mx1, 1));
        mx1 = fmaxf(mx1, __shfl_xor_sync(0xffffffffu, mx1, 2));

        float mn0 = fmaxf(m0r, mx0), mn1 = fmaxf(m1r, mx1);
        float al0 = __expf(m0r - mn0), al1 = __expf(m1r - mn1);
        float s0 = 0.f, s1 = 0.f;
#pragma unroll
        for (int nt = 0; nt < 8; nt++) {
            S[nt][0] = __expf(S[nt][0] - mn0);
            S[nt][1] = __expf(S[nt][1] - mn0);
            S[nt][2] = __expf(S[nt][2] - mn1);
            S[nt][3] = __expf(S[nt][3] - mn1);
            s0 += S[nt][0] + S[nt][1];
            s1 += S[nt][2] + S[nt][3];
        }
        s0 += __shfl_xor_sync(0xffffffffu, s0, 1);
        s0 += __shfl_xor_sync(0xffffffffu, s0, 2);
        s1 += __shfl_xor_sync(0xffffffffu, s1, 1);
        s1 += __shfl_xor_sync(0xffffffffu, s1, 2);
        l0r = l0r * al0 + s0;
        l1r = l1r * al1 + s1;
        m0r = mn0; m1r = mn1;
#pragma unroll
        for (int nt = 0; nt < 12; nt++) {
            O[nt][0] *= al0; O[nt][1] *= al0;
            O[nt][2] *= al1; O[nt][3] *= al1;
        }

#pragma unroll
        for (int ks = 0; ks < 4; ks++) {
            uint32_t a0 = packh2(S[2*ks][0],   S[2*ks][1]);
            uint32_t a1 = packh2(S[2*ks][2],   S[2*ks][3]);
            uint32_t a2 = packh2(S[2*ks+1][0], S[2*ks+1][1]);
            uint32_t a3 = packh2(S[2*ks+1][2], S[2*ks+1][3]);
#pragma unroll
            for (int bk = 0; bk < 6; bk++) {
                uint32_t b0, b1, b2, b3;
                ldsm4(b0, b1, b2, b3,
                      vsb + (uint32_t)((bRow + bk * 16) * VTLDH + ks * 16 + bCol) * 2);
                mma_h(O[2*bk],   a0, a1, a2, a3, b0, b1);
                mma_h(O[2*bk+1], a0, a1, a2, a3, b2, b3);
            }
        }
        // (no bottom sync: next iteration's top sync fences these reads)
    }

    float inv0 = 1.f / l0r, inv1 = 1.f / l1r;
    __half* outb = g_atth + ((size_t)b * SEQ + row0) * DIMC + hh * HD;
#pragma unroll
    for (int nt = 0; nt < 12; nt++) {
        int d = nt * 8 + 2 * j;
        *(uint32_t*)(outb + d) = packh2(O[nt][0] * inv0, O[nt][1] * inv0);
        *(uint32_t*)(outb + (size_t)8 * DIMC + d) = packh2(O[nt][2] * inv1, O[nt][3] * inv1);
    }
}

// ---------------------------------------------------------------------------
// Launch
// Inputs: 0=x, 1=mask (ignored, causal), 2=w_qkv, 3=b_qkv, 4=w_proj, 5=b_proj
// ---------------------------------------------------------------------------
extern "C" void kernel_launch(void* const* d_in, const int* in_sizes, int n_in,
                              void* d_out, int out_size)
{
    const float* x      = (const float*)d_in[0];
    const float* w_qkv  = (const float*)d_in[2];
    const float* b_qkv  = (const float*)d_in[3];
    const float* w_proj = (const float*)d_in[4];
    const float* b_proj = (const float*)d_in[5];
    float* out = (float*)d_out;

    cudaFuncSetAttribute(attn_mma, cudaFuncAttributeMaxDynamicSharedMemorySize,
                         ATTN_SMEM);
    cudaFuncSetAttribute((void*)gemm_h<0, 256, 2, 8>,
                         cudaFuncAttributeMaxDynamicSharedMemorySize, GEMM_SMEM_256);
    cudaFuncSetAttribute((void*)gemm_h<1, 128, 4, 4>,
                         cudaFuncAttributeMaxDynamicSharedMemorySize, GEMM_SMEM_128);

    __half *xh, *wqh, *wph, *ath;
    cudaGetSymbolAddress((void**)&xh,  g_xh);
    cudaGetSymbolAddress((void**)&wqh, g_wqh);
    cudaGetSymbolAddress((void**)&wph, g_wph);
    cudaGetSymbolAddress((void**)&ath, g_atth);

    // pack operands to fp16
    pack_h_kernel<<<(MTOT * DIMC / 8 + 255) / 256, 256>>>(x, xh, MTOT * DIMC / 8);
    pack_h_kernel<<<(3 * DIMC * DIMC / 8 + 255) / 256, 256>>>(w_qkv, wqh, 3 * DIMC * DIMC / 8);
    pack_h_kernel<<<(DIMC * DIMC / 8 + 255) / 256, 256>>>(w_proj, wph, DIMC * DIMC / 8);

    // QKV: M=8192, N=2304 (CTA tile 128x256, 512 threads)
    gemm_h<0, 256, 2, 8><<<dim3(2304 / 256, MTOT / 128), 512, GEMM_SMEM_256>>>(
        xh, wqh, b_qkv, nullptr);

    // RoPE (q f32 in place, k -> fp16)
    rope_kernel<<<(BATCH * NH * SEQ * 48) / 256, 256>>>();

    // Attention (fp16, 3-stage ring, 2 CTAs/SM)
    attn_mma<<<dim3(SEQ / 128, NH, BATCH), 256, ATTN_SMEM>>>();

    // Projection: M=8192, N=768 (CTA tile 128x128, 512 threads)
    gemm_h<1, 128, 4, 4><<<dim3(DIMC / 128, MTOT / 128), 512, GEMM_SMEM_128>>>(
        ath, wph, b_proj, out);
}

// round 16
// speedup vs baseline: 1.0450x; 1.0450x over previous
#include <cuda_runtime.h>
#include <cuda_fp16.h>
#include <math.h>
#include <stdint.h>

#define DIMC 768
#define NH 8
#define HD 96
#define BATCH 4
#define SEQ 2048
#define MTOT (BATCH*SEQ)

// Scratch (static device arrays; no cudaMalloc allowed)
__device__ float g_q[(size_t)BATCH*NH*SEQ*HD];
__device__ float g_k[(size_t)BATCH*NH*SEQ*HD];
__device__ __half g_kh[(size_t)BATCH*NH*SEQ*HD];    // K after rope, fp16 [b,h,t,d]
__device__ __half g_vth[(size_t)BATCH*NH*HD*SEQ];   // V transposed fp16 [b,h,d,t]
__device__ __half g_atth[(size_t)MTOT*DIMC];        // attention out, fp16
__device__ __half g_xh[(size_t)MTOT*DIMC];          // x, fp16
__device__ __half g_wqh[(size_t)3*DIMC*DIMC];       // w_qkv, fp16
__device__ __half g_wph[(size_t)DIMC*DIMC];         // w_proj, fp16

// ---------------------------------------------------------------------------
// helpers
// ---------------------------------------------------------------------------
__device__ __forceinline__ uint32_t smem_u32(const void* p) {
    uint32_t a;
    asm("{ .reg .u64 t; cvta.to.shared.u64 t, %1; cvt.u32.u64 %0, t; }" : "=r"(a) : "l"(p));
    return a;
}
__device__ __forceinline__ void cp16(uint32_t s, const void* g) {
    asm volatile("cp.async.ca.shared.global [%0], [%1], 16;" :: "r"(s), "l"(g) : "memory");
}
__device__ __forceinline__ void cp_commit() {
    asm volatile("cp.async.commit_group;" ::: "memory");
}
__device__ __forceinline__ void cp_wait1() {
    asm volatile("cp.async.wait_group 1;" ::: "memory");
}
__device__ __forceinline__ void cp_wait0() {
    asm volatile("cp.async.wait_group 0;" ::: "memory");
}
// pack two f32 -> f16x2 (x0 -> low half)
__device__ __forceinline__ uint32_t packh2(float x0, float x1) {
    uint32_t r;
    asm("cvt.rn.f16x2.f32 %0, %1, %2;" : "=r"(r) : "f"(x1), "f"(x0));
    return r;
}
// packed half2 exp2 approx
__device__ __forceinline__ uint32_t h2exp2(uint32_t x) {
    uint32_t r;
    asm("ex2.approx.f16x2 %0, %1;" : "=r"(r) : "r"(x));
    return r;
}
__device__ __forceinline__ void ldsm4(uint32_t& r0, uint32_t& r1, uint32_t& r2,
                                      uint32_t& r3, uint32_t addr) {
    asm volatile("ldmatrix.sync.aligned.m8n8.x4.shared.b16 {%0,%1,%2,%3}, [%4];"
                 : "=r"(r0), "=r"(r1), "=r"(r2), "=r"(r3) : "r"(addr));
}
// fp16 inputs, f32 accum, k16
__device__ __forceinline__ void mma_h(float d[4], uint32_t a0, uint32_t a1,
                                      uint32_t a2, uint32_t a3,
                                      uint32_t b0, uint32_t b1) {
    asm volatile(
        "mma.sync.aligned.m16n8k16.row.col.f32.f16.f16.f32 "
        "{%0,%1,%2,%3},{%4,%5,%6,%7},{%8,%9},{%0,%1,%2,%3};"
        : "+f"(d[0]), "+f"(d[1]), "+f"(d[2]), "+f"(d[3])
        : "r"(a0), "r"(a1), "r"(a2), "r"(a3), "r"(b0), "r"(b1));
}

// ---------------------------------------------------------------------------
// pack: f32 -> fp16 (8 floats per thread)
// ---------------------------------------------------------------------------
__global__ __launch_bounds__(256)
void pack_h_kernel(const float* __restrict__ src, __half* __restrict__ dst, int n8)
{
    int i = blockIdx.x * blockDim.x + threadIdx.x;
    if (i < n8) {
        float4 v0 = ((const float4*)src)[2*i];
        float4 v1 = ((const float4*)src)[2*i+1];
        uint4 o;
        o.x = packh2(v0.x, v0.y);
        o.y = packh2(v0.z, v0.w);
        o.z = packh2(v1.x, v1.y);
        o.w = packh2(v1.z, v1.w);
        ((uint4*)dst)[i] = o;
    }
}

// ---------------------------------------------------------------------------
// GEMM (R14 winner): fp16 mma, 512 threads, CTA tile 128 x BN, warp grid
// WM x WN, k-chunk 32, 3-stage cp.async ring.
// MODE 0: scatter q/k -> f32, v -> g_vth fp16 transposed. MODE 1: write Cout.
// ---------------------------------------------------------------------------
#define KCH 40   // half stride per row (80B, odd multiple of 16B)

template<int MODE, int BN, int WM, int WN>
__global__ __launch_bounds__(512, 1)
void gemm_h(const __half* __restrict__ A, const __half* __restrict__ W,
            const float* __restrict__ bias, float* __restrict__ Cout)
{
    constexpr int ASZ = 128 * KCH;
    constexpr int WSZ = BN * KCH;
    constexpr int STG = ASZ + WSZ;
    constexpr int MT  = 128 / (WM * 16);
    constexpr int NT  = BN / (WN * 8);
    constexpr int NBK = NT / 2;
    constexpr int NIT = (128 + BN) * 4 / 512;

    extern __shared__ __half smh[];
    uint32_t smb = smem_u32(smh);

    int tid = threadIdx.x;
    int lane = tid & 31;
    int wid = tid >> 5;
    int g = lane >> 2, j = lane & 3;
    int wm = wid % WM, wn = wid / WM;
    int m0 = blockIdx.y * 128;
    int n0 = blockIdx.x * BN;

    auto issue = [&](int c) {
        uint32_t stb = smb + (uint32_t)((c % 3) * STG) * 2;
#pragma unroll
        for (int it = 0; it < NIT; it++) {
            int f = tid + it * 512;
            int row = f >> 2;
            int ch = (f & 3) * 8;
            if (row < 128) {
                cp16(stb + (uint32_t)(row * KCH + ch) * 2,
                     A + (size_t)(m0 + row) * DIMC + c * 32 + ch);
            } else {
                int wrow = row - 128;
                cp16(stb + (uint32_t)(ASZ + wrow * KCH + ch) * 2,
                     W + (size_t)(n0 + wrow) * DIMC + c * 32 + ch);
            }
        }
    };

    int aRowB = wm * (MT * 16) + (lane & 7) + ((lane >> 3) & 1) * 8;
    int aCol  = ((lane >> 4) & 1) * 8;
    int bRowB = wn * (NT * 8) + (lane & 7) + ((lane >> 4) & 1) * 8;
    int bCol  = ((lane >> 3) & 1) * 8;

    float Cf[MT][NT][4];
#pragma unroll
    for (int mt = 0; mt < MT; mt++)
#pragma unroll
        for (int nt = 0; nt < NT; nt++)
#pragma unroll
            for (int r = 0; r < 4; r++) Cf[mt][nt][r] = 0.f;

    issue(0); cp_commit();
    issue(1); cp_commit();

    const int NC = DIMC / 32;
    for (int c = 0; c < NC; c++) {
        cp_wait1();
        __syncthreads();
        if (c + 2 < NC) issue(c + 2);
        cp_commit();

        uint32_t stA = smb + (uint32_t)((c % 3) * STG) * 2;
        uint32_t stW = stA + (uint32_t)ASZ * 2;

#pragma unroll
        for (int ks = 0; ks < 2; ks++) {
            uint32_t a[MT][4], b[NT][2];
#pragma unroll
            for (int mt = 0; mt < MT; mt++)
                ldsm4(a[mt][0], a[mt][1], a[mt][2], a[mt][3],
                      stA + (uint32_t)((aRowB + mt * 16) * KCH + ks * 16 + aCol) * 2);
#pragma unroll
            for (int bk = 0; bk < NBK; bk++)
                ldsm4(b[2*bk][0], b[2*bk][1], b[2*bk+1][0], b[2*bk+1][1],
                      stW + (uint32_t)((bRowB + bk * 16) * KCH + ks * 16 + bCol) * 2);
#pragma unroll
            for (int mt = 0; mt < MT; mt++)
#pragma unroll
                for (int nt = 0; nt < NT; nt++)
                    mma_h(Cf[mt][nt], a[mt][0], a[mt][1], a[mt][2], a[mt][3],
                          b[nt][0], b[nt][1]);
        }
    }

    // epilogue
#pragma unroll
    for (int mt = 0; mt < MT; mt++) {
        int row0 = m0 + wm * (MT * 16) + mt * 16 + g;
#pragma unroll
        for (int nt = 0; nt < NT; nt++) {
            int col = n0 + wn * (NT * 8) + nt * 8 + 2 * j;
            float b0 = bias[col], b1 = bias[col + 1];
            float2 v0 = make_float2(Cf[mt][nt][0] + b0, Cf[mt][nt][1] + b1);
            float2 v1 = make_float2(Cf[mt][nt][2] + b0, Cf[mt][nt][3] + b1);
            if (MODE == 1) {
                *(float2*)(Cout + (size_t)row0 * DIMC + col) = v0;
                *(float2*)(Cout + (size_t)(row0 + 8) * DIMC + col) = v1;
            } else {
                int s = (col >= 2 * DIMC) ? 2 : (col >= DIMC ? 1 : 0);
                int rr = col - s * DIMC;
                int hh = rr / HD;
                int d = rr - hh * HD;
                int bb0 = row0 >> 11, t0 = row0 & (SEQ - 1);
                int r1 = row0 + 8;
                int bb1 = r1 >> 11, t1 = r1 & (SEQ - 1);
                if (s == 2) {
                    __half* dv0 = g_vth + ((size_t)(bb0 * NH + hh) * HD + d) * SEQ + t0;
                    dv0[0] = __float2half_rn(v0.x); dv0[SEQ] = __float2half_rn(v0.y);
                    __half* dv1 = g_vth + ((size_t)(bb1 * NH + hh) * HD + d) * SEQ + t1;
                    dv1[0] = __float2half_rn(v1.x); dv1[SEQ] = __float2half_rn(v1.y);
                } else {
                    float* base = (s == 0) ? g_q : g_k;
                    *(float2*)(base + ((size_t)(bb0 * NH + hh) * SEQ + t0) * HD + d) = v0;
                    *(float2*)(base + ((size_t)(bb1 * NH + hh) * SEQ + t1) * HD + d) = v1;
                }
            }
        }
    }
}

#define GEMM_SMEM_256 (3*(128+256)*KCH*2)
#define GEMM_SMEM_128 (3*(128+128)*KCH*2)

// ---------------------------------------------------------------------------
// RoPE: q in place (f32), k -> g_kh (fp16).
// ---------------------------------------------------------------------------
__global__ __launch_bounds__(256)
void rope_kernel()
{
    int idx = blockIdx.x * blockDim.x + threadIdx.x;
    int j = idx % 48;
    int rest = idx / 48;
    int t = rest & (SEQ - 1);
    int bh = rest >> 11;

    float freq = exp2f(-(2.f * j / 96.f) * 13.287712379549449f);
    float ang = (float)t * freq;
    float sn, cs;
    sincosf(ang, &sn, &cs);

    size_t base = ((size_t)bh * SEQ + t) * HD;
    float q1 = g_q[base + j], q2 = g_q[base + j + 48];
    g_q[base + j]      = q1 * cs - q2 * sn;
    g_q[base + j + 48] = q2 * cs + q1 * sn;
    float k1 = g_k[base + j], k2 = g_k[base + j + 48];
    g_kh[base + j]      = __float2half_rn(k1 * cs - k2 * sn);
    g_kh[base + j + 48] = __float2half_rn(k2 * cs + k1 * sn);
}

// ---------------------------------------------------------------------------
// Flash attention v9 (base = R14 winner: 2-stage ring, 2 CTAs/SM):
//  - softmax in log2 domain: Q prescaled by scale*log2e; P = ex2.approx.f16x2
//    (half the MUFU ops; result IS the PV A-fragment, no cvt pack)
//  - row-sum l via ones-row (row 96) appended to V: l accumulates as O col 96
//    through the same PV mma + alpha rescale (no shuffle sum-reduce).
// ---------------------------------------------------------------------------
#define QLDH 104
#define KLDH 104
#define VTLDH 72
#define VROWS 112                          // 96 data + ones row 96 + zeros 97..111
#define KVSTGH (64*KLDH + VROWS*VTLDH)
#define ATTN_SMEM ((128*QLDH + 2*KVSTGH) * 2)   // 85504 B -> 2 CTAs/SM

__global__ __launch_bounds__(256, 2)
void attn_mma()
{
    extern __shared__ __half smh[];
    __half* Qh = smh;
    __half* KV = smh + 128 * QLDH;

    int qt = gridDim.x - 1 - blockIdx.x;
    int hh = blockIdx.y, b = blockIdx.z;
    int tid = threadIdx.x;
    int lane = tid & 31;
    int wid = tid >> 5;
    int g = lane >> 2, j = lane & 3;
    const float scale = rsqrtf((float)HD) * 1.4426950408889634f;   // *log2(e)

    const float* Qg = g_q + ((size_t)(b * NH + hh) * SEQ + (size_t)qt * 128) * HD;
    const __half* Kg = g_kh + ((size_t)(b * NH + hh) * SEQ) * HD;
    const __half* Vtg = g_vth + ((size_t)(b * NH + hh) * HD) * SEQ;

    int nkt = 2 * qt + 2;

    auto issue_kv = [&](int kt) {
        int st = kt & 1;
        __half* Ks = KV + st * KVSTGH;
        __half* Vs = Ks + 64 * KLDH;
        const __half* kp = Kg + (size_t)kt * 64 * HD;
#pragma unroll
        for (int it = 0; it < 3; it++) {
            int f = tid + it * 256;
            int r = f / 12, ch = f % 12;
            cp16(smem_u32(Ks + r * KLDH + ch * 8), kp + (size_t)r * HD + ch * 8);
        }
        const __half* vp = Vtg + kt * 64;
#pragma unroll
        for (int it = 0; it < 3; it++) {
            int f = tid + it * 256;
            int d = f >> 3, ch = f & 7;
            cp16(smem_u32(Vs + d * VTLDH + ch * 8), vp + (size_t)d * SEQ + ch * 8);
        }
    };

    // init constant V rows (96=ones, 97..111=zeros) in BOTH stages; cp.async
    // never touches rows >= 96, so this persists.
    for (int f = tid; f < 2 * 16 * VTLDH; f += 256) {
        int st = f / (16 * VTLDH);
        int rem = f - st * (16 * VTLDH);
        int r = 96 + rem / VTLDH;
        int c = rem % VTLDH;
        __half v = (r == 96) ? __float2half(1.f) : __float2half(0.f);
        (KV + st * KVSTGH + 64 * KLDH)[r * VTLDH + c] = v;
    }

    issue_kv(0); cp_commit();

    for (int f = tid; f < 128 * 24; f += 256) {
        int r = f / 24, c4 = (f % 24) * 4;
        float4 v = *(const float4*)(Qg + (size_t)r * HD + c4);
        uint32_t h0 = packh2(v.x * scale, v.y * scale);
        uint32_t h1 = packh2(v.z * scale, v.w * scale);
        uint32_t* dst = (uint32_t*)(Qh + r * QLDH + c4);
        dst[0] = h0; dst[1] = h1;
    }

    uint32_t qsb = smem_u32(Qh);
    uint32_t kvb = smem_u32(KV);
    int qRow = wid * 16 + (lane & 7) + ((lane >> 3) & 1) * 8;
    int qCol = ((lane >> 4) & 1) * 8;
    int bRow = (lane & 7) + ((lane >> 4) & 1) * 8;
    int bCol = ((lane >> 3) & 1) * 8;

    float m0r = -1e30f, m1r = -1e30f;
    float O[13][4];      // O[12] col 96 = running row-sum l (lane j==0)
#pragma unroll
    for (int nt = 0; nt < 13; nt++)
#pragma unroll
        for (int r = 0; r < 4; r++) O[nt][r] = 0.f;

    int row0 = qt * 128 + wid * 16 + g;

    for (int kt = 0; kt < nkt; kt++) {
        cp_wait0();
        __syncthreads();     // stage kt visible; all warps done reading kt-1
        if (kt + 1 < nkt) issue_kv(kt + 1);
        cp_commit();

        uint32_t ksb = kvb + (uint32_t)((kt & 1) * KVSTGH) * 2;
        uint32_t vsb = ksb + (uint32_t)(64 * KLDH) * 2;

        // ---- S = Q @ K^T (log2-scaled) ----
        float S[8][4];
#pragma unroll
        for (int nt = 0; nt < 8; nt++)
#pragma unroll
            for (int r = 0; r < 4; r++) S[nt][r] = 0.f;

#pragma unroll
        for (int ks = 0; ks < 6; ks++) {
            uint32_t a0, a1, a2, a3;
            ldsm4(a0, a1, a2, a3, qsb + (uint32_t)(qRow * QLDH + ks * 16 + qCol) * 2);
#pragma unroll
            for (int bk = 0; bk < 4; bk++) {
                uint32_t b0, b1, b2, b3;
                ldsm4(b0, b1, b2, b3,
                      ksb + (uint32_t)((bRow + bk * 16) * KLDH + ks * 16 + bCol) * 2);
                mma_h(S[2*bk],   a0, a1, a2, a3, b0, b1);
                mma_h(S[2*bk+1], a0, a1, a2, a3, b2, b3);
            }
        }

        if (kt >= nkt - 2) {
            int colb = kt * 64;
#pragma unroll
            for (int nt = 0; nt < 8; nt++) {
                int c0 = colb + nt * 8 + 2 * j;
                if (c0 > row0)     S[nt][0] = -1e30f;
                if (c0 + 1 > row0) S[nt][1] = -1e30f;
                if (c0 > row0 + 8)     S[nt][2] = -1e30f;
                if (c0 + 1 > row0 + 8) S[nt][3] = -1e30f;
            }
        }

        // ---- online softmax (log2 domain, P via packed half2 exp2) ----
        float mx0 = -1e30f, mx1 = -1e30f;
#pragma unroll
        for (int nt = 0; nt < 8; nt++) {
            mx0 = fmaxf(mx0, fmaxf(S[nt][0], S[nt][1]));
            mx1 = fmaxf(mx1, fmaxf(S[nt][2], S[nt][3]));
        }
        mx0 = fmaxf(mx0, __shfl_xor_sync(0xffffffffu, mx0, 1));
        mx0 = fmaxf(mx0, __shfl_xor_sync(0xffffffffu, mx0, 2));
        mx1 = fmaxf(mx1, __shfl_xor_sync(0xffffffffu, mx1, 1));
        mx1 = fmaxf(mx1, __shfl_xor_sync(0xffffffffu, mx1, 2));

        float mn0 = fmaxf(m0r, mx0), mn1 = fmaxf(m1r, mx1);
        float al0 = exp2f(m0r - mn0), al1 = exp2f(m1r - mn1);
        m0r = mn0; m1r = mn1;
#pragma unroll
        for (int nt = 0; nt < 13; nt++) {
            O[nt][0] *= al0; O[nt][1] *= al0;
            O[nt][2] *= al1; O[nt][3] *= al1;
        }

        // P fragments directly in packed half2 (ph[nt][0]: rows g; [1]: rows g+8)
        uint32_t ph[8][2];
#pragma unroll
        for (int nt = 0; nt < 8; nt++) {
            ph[nt][0] = h2exp2(packh2(S[nt][0] - mn0, S[nt][1] - mn0));
            ph[nt][1] = h2exp2(packh2(S[nt][2] - mn1, S[nt][3] - mn1));
        }

        // ---- O += P @ V (cols 0..95 data, col 96 = l via ones-row) ----
#pragma unroll
        for (int ks = 0; ks < 4; ks++) {
            uint32_t a0 = ph[2*ks][0];
            uint32_t a1 = ph[2*ks][1];
            uint32_t a2 = ph[2*ks+1][0];
            uint32_t a3 = ph[2*ks+1][1];
#pragma unroll
            for (int bk = 0; bk < 7; bk++) {
                uint32_t b0, b1, b2, b3;
                ldsm4(b0, b1, b2, b3,
                      vsb + (uint32_t)((bRow + bk * 16) * VTLDH + ks * 16 + bCol) * 2);
                mma_h(O[2*bk], a0, a1, a2, a3, b0, b1);
                if (bk < 6) mma_h(O[2*bk+1], a0, a1, a2, a3, b2, b3);
            }
        }
    }

    // l lives in O[12][0]/[2] of lanes with j==0 (col 96); broadcast in quad
    float l0r = __shfl_sync(0xffffffffu, O[12][0], lane & ~3);
    float l1r = __shfl_sync(0xffffffffu, O[12][2], lane & ~3);
    float inv0 = 1.f / l0r, inv1 = 1.f / l1r;
    __half* outb = g_atth + ((size_t)b * SEQ + row0) * DIMC + hh * HD;
#pragma unroll
    for (int nt = 0; nt < 12; nt++) {
        int d = nt * 8 + 2 * j;
        *(uint32_t*)(outb + d) = packh2(O[nt][0] * inv0, O[nt][1] * inv0);
        *(uint32_t*)(outb + (size_t)8 * DIMC + d) = packh2(O[nt][2] * inv1, O[nt][3] * inv1);
    }
}

// ---------------------------------------------------------------------------
// Launch
// Inputs: 0=x, 1=mask (ignored, causal), 2=w_qkv, 3=b_qkv, 4=w_proj, 5=b_proj
// ---------------------------------------------------------------------------
extern "C" void kernel_launch(void* const* d_in, const int* in_sizes, int n_in,
                              void* d_out, int out_size)
{
    const float* x      = (const float*)d_in[0];
    const float* w_qkv  = (const float*)d_in[2];
    const float* b_qkv  = (const float*)d_in[3];
    const float* w_proj = (const float*)d_in[4];
    const float* b_proj = (const float*)d_in[5];
    float* out = (float*)d_out;

    cudaFuncSetAttribute(attn_mma, cudaFuncAttributeMaxDynamicSharedMemorySize,
                         ATTN_SMEM);
    cudaFuncSetAttribute((void*)gemm_h<0, 256, 2, 8>,
                         cudaFuncAttributeMaxDynamicSharedMemorySize, GEMM_SMEM_256);
    cudaFuncSetAttribute((void*)gemm_h<1, 128, 4, 4>,
                         cudaFuncAttributeMaxDynamicSharedMemorySize, GEMM_SMEM_128);

    __half *xh, *wqh, *wph, *ath;
    cudaGetSymbolAddress((void**)&xh,  g_xh);
    cudaGetSymbolAddress((void**)&wqh, g_wqh);
    cudaGetSymbolAddress((void**)&wph, g_wph);
    cudaGetSymbolAddress((void**)&ath, g_atth);

    // pack operands to fp16
    pack_h_kernel<<<(MTOT * DIMC / 8 + 255) / 256, 256>>>(x, xh, MTOT * DIMC / 8);
    pack_h_kernel<<<(3 * DIMC * DIMC / 8 + 255) / 256, 256>>>(w_qkv, wqh, 3 * DIMC * DIMC / 8);
    pack_h_kernel<<<(DIMC * DIMC / 8 + 255) / 256, 256>>>(w_proj, wph, DIMC * DIMC / 8);

    // QKV: M=8192, N=2304 (CTA tile 128x256, 512 threads)
    gemm_h<0, 256, 2, 8><<<dim3(2304 / 256, MTOT / 128), 512, GEMM_SMEM_256>>>(
        xh, wqh, b_qkv, nullptr);

    // RoPE (q f32 in place, k -> fp16)
    rope_kernel<<<(BATCH * NH * SEQ * 48) / 256, 256>>>();

    // Attention (fp16, 2-stage ring, 2 CTAs/SM, ex2.approx softmax)
    attn_mma<<<dim3(SEQ / 128, NH, BATCH), 256, ATTN_SMEM>>>();

    // Projection: M=8192, N=768 (CTA tile 128x128, 512 threads)
    gemm_h<1, 128, 4, 4><<<dim3(DIMC / 128, MTOT / 128), 512, GEMM_SMEM_128>>>(
        ath, wph, b_proj, out);
}

// round 17
// speedup vs baseline: 1.0532x; 1.0079x over previous
#include <cuda_runtime.h>
#include <cuda_fp16.h>
#include <math.h>
#include <stdint.h>

#define DIMC 768
#define NH 8
#define HD 96
#define BATCH 4
#define SEQ 2048
#define MTOT (BATCH*SEQ)

// Scratch (static device arrays; no cudaMalloc allowed)
__device__ float g_q[(size_t)BATCH*NH*SEQ*HD];
__device__ float g_k[(size_t)BATCH*NH*SEQ*HD];
__device__ __half g_kh[(size_t)BATCH*NH*SEQ*HD];    // K after rope, fp16 [b,h,t,d]
__device__ __half g_vth[(size_t)BATCH*NH*HD*SEQ];   // V transposed fp16 [b,h,d,t]
__device__ __half g_atth[(size_t)MTOT*DIMC];        // attention out, fp16
__device__ __half g_xh[(size_t)MTOT*DIMC];          // x, fp16
__device__ __half g_wqh[(size_t)3*DIMC*DIMC];       // w_qkv, fp16
__device__ __half g_wph[(size_t)DIMC*DIMC];         // w_proj, fp16

// ---------------------------------------------------------------------------
// helpers
// ---------------------------------------------------------------------------
__device__ __forceinline__ uint32_t smem_u32(const void* p) {
    uint32_t a;
    asm("{ .reg .u64 t; cvta.to.shared.u64 t, %1; cvt.u32.u64 %0, t; }" : "=r"(a) : "l"(p));
    return a;
}
// L1-bypassing bulk copy (no reuse in L1; keep L1 for ldsm)
__device__ __forceinline__ void cp16(uint32_t s, const void* g) {
    asm volatile("cp.async.cg.shared.global [%0], [%1], 16;" :: "r"(s), "l"(g) : "memory");
}
__device__ __forceinline__ void cp_commit() {
    asm volatile("cp.async.commit_group;" ::: "memory");
}
__device__ __forceinline__ void cp_wait1() {
    asm volatile("cp.async.wait_group 1;" ::: "memory");
}
__device__ __forceinline__ void cp_wait0() {
    asm volatile("cp.async.wait_group 0;" ::: "memory");
}
// pack two f32 -> f16x2 (x0 -> low half)
__device__ __forceinline__ uint32_t packh2(float x0, float x1) {
    uint32_t r;
    asm("cvt.rn.f16x2.f32 %0, %1, %2;" : "=r"(r) : "f"(x1), "f"(x0));
    return r;
}
// packed half2 exp2 approx
__device__ __forceinline__ uint32_t h2exp2(uint32_t x) {
    uint32_t r;
    asm("ex2.approx.f16x2 %0, %1;" : "=r"(r) : "r"(x));
    return r;
}
__device__ __forceinline__ void ldsm4(uint32_t& r0, uint32_t& r1, uint32_t& r2,
                                      uint32_t& r3, uint32_t addr) {
    asm volatile("ldmatrix.sync.aligned.m8n8.x4.shared.b16 {%0,%1,%2,%3}, [%4];"
                 : "=r"(r0), "=r"(r1), "=r"(r2), "=r"(r3) : "r"(addr));
}
// fp16 inputs, f32 accum, k16
__device__ __forceinline__ void mma_h(float d[4], uint32_t a0, uint32_t a1,
                                      uint32_t a2, uint32_t a3,
                                      uint32_t b0, uint32_t b1) {
    asm volatile(
        "mma.sync.aligned.m16n8k16.row.col.f32.f16.f16.f32 "
        "{%0,%1,%2,%3},{%4,%5,%6,%7},{%8,%9},{%0,%1,%2,%3};"
        : "+f"(d[0]), "+f"(d[1]), "+f"(d[2]), "+f"(d[3])
        : "r"(a0), "r"(a1), "r"(a2), "r"(a3), "r"(b0), "r"(b1));
}

// ---------------------------------------------------------------------------
// fused pack: x, w_qkv, w_proj -> fp16 in ONE launch
// ---------------------------------------------------------------------------
#define NX8  (MTOT*DIMC/8)
#define NWQ8 (3*DIMC*DIMC/8)
#define NWP8 (DIMC*DIMC/8)

__global__ __launch_bounds__(256)
void pack_all_kernel(const float* __restrict__ x, const float* __restrict__ wq,
                     const float* __restrict__ wp)
{
    int i = blockIdx.x * blockDim.x + threadIdx.x;
    const float* src;
    __half* dst;
    int idx;
    if (i < NX8)                 { src = x;  dst = g_xh;  idx = i; }
    else if (i < NX8 + NWQ8)     { src = wq; dst = g_wqh; idx = i - NX8; }
    else if (i < NX8 + NWQ8 + NWP8) { src = wp; dst = g_wph; idx = i - NX8 - NWQ8; }
    else return;

    float4 v0 = ((const float4*)src)[2*idx];
    float4 v1 = ((const float4*)src)[2*idx+1];
    uint4 o;
    o.x = packh2(v0.x, v0.y);
    o.y = packh2(v0.z, v0.w);
    o.z = packh2(v1.x, v1.y);
    o.w = packh2(v1.z, v1.w);
    ((uint4*)dst)[idx] = o;
}

// ---------------------------------------------------------------------------
// GEMM (R14 winner): fp16 mma, 512 threads, CTA tile 128 x BN, warp grid
// WM x WN, k-chunk 32, 3-stage cp.async ring.
// MODE 0: scatter q/k -> f32, v -> g_vth fp16 transposed. MODE 1: write Cout.
// ---------------------------------------------------------------------------
#define KCH 40   // half stride per row (80B, odd multiple of 16B)

template<int MODE, int BN, int WM, int WN>
__global__ __launch_bounds__(512, 1)
void gemm_h(const __half* __restrict__ A, const __half* __restrict__ W,
            const float* __restrict__ bias, float* __restrict__ Cout)
{
    constexpr int ASZ = 128 * KCH;
    constexpr int WSZ = BN * KCH;
    constexpr int STG = ASZ + WSZ;
    constexpr int MT  = 128 / (WM * 16);
    constexpr int NT  = BN / (WN * 8);
    constexpr int NBK = NT / 2;
    constexpr int NIT = (128 + BN) * 4 / 512;

    extern __shared__ __half smh[];
    uint32_t smb = smem_u32(smh);

    int tid = threadIdx.x;
    int lane = tid & 31;
    int wid = tid >> 5;
    int g = lane >> 2, j = lane & 3;
    int wm = wid % WM, wn = wid / WM;
    int m0 = blockIdx.y * 128;
    int n0 = blockIdx.x * BN;

    auto issue = [&](int c) {
        uint32_t stb = smb + (uint32_t)((c % 3) * STG) * 2;
#pragma unroll
        for (int it = 0; it < NIT; it++) {
            int f = tid + it * 512;
            int row = f >> 2;
            int ch = (f & 3) * 8;
            if (row < 128) {
                cp16(stb + (uint32_t)(row * KCH + ch) * 2,
                     A + (size_t)(m0 + row) * DIMC + c * 32 + ch);
            } else {
                int wrow = row - 128;
                cp16(stb + (uint32_t)(ASZ + wrow * KCH + ch) * 2,
                     W + (size_t)(n0 + wrow) * DIMC + c * 32 + ch);
            }
        }
    };

    int aRowB = wm * (MT * 16) + (lane & 7) + ((lane >> 3) & 1) * 8;
    int aCol  = ((lane >> 4) & 1) * 8;
    int bRowB = wn * (NT * 8) + (lane & 7) + ((lane >> 4) & 1) * 8;
    int bCol  = ((lane >> 3) & 1) * 8;

    float Cf[MT][NT][4];
#pragma unroll
    for (int mt = 0; mt < MT; mt++)
#pragma unroll
        for (int nt = 0; nt < NT; nt++)
#pragma unroll
            for (int r = 0; r < 4; r++) Cf[mt][nt][r] = 0.f;

    issue(0); cp_commit();
    issue(1); cp_commit();

    const int NC = DIMC / 32;
    for (int c = 0; c < NC; c++) {
        cp_wait1();
        __syncthreads();
        if (c + 2 < NC) issue(c + 2);
        cp_commit();

        uint32_t stA = smb + (uint32_t)((c % 3) * STG) * 2;
        uint32_t stW = stA + (uint32_t)ASZ * 2;

#pragma unroll
        for (int ks = 0; ks < 2; ks++) {
            uint32_t a[MT][4], b[NT][2];
#pragma unroll
            for (int mt = 0; mt < MT; mt++)
                ldsm4(a[mt][0], a[mt][1], a[mt][2], a[mt][3],
                      stA + (uint32_t)((aRowB + mt * 16) * KCH + ks * 16 + aCol) * 2);
#pragma unroll
            for (int bk = 0; bk < NBK; bk++)
                ldsm4(b[2*bk][0], b[2*bk][1], b[2*bk+1][0], b[2*bk+1][1],
                      stW + (uint32_t)((bRowB + bk * 16) * KCH + ks * 16 + bCol) * 2);
#pragma unroll
            for (int mt = 0; mt < MT; mt++)
#pragma unroll
                for (int nt = 0; nt < NT; nt++)
                    mma_h(Cf[mt][nt], a[mt][0], a[mt][1], a[mt][2], a[mt][3],
                          b[nt][0], b[nt][1]);
        }
    }

    // epilogue
#pragma unroll
    for (int mt = 0; mt < MT; mt++) {
        int row0 = m0 + wm * (MT * 16) + mt * 16 + g;
#pragma unroll
        for (int nt = 0; nt < NT; nt++) {
            int col = n0 + wn * (NT * 8) + nt * 8 + 2 * j;
            float b0 = bias[col], b1 = bias[col + 1];
            float2 v0 = make_float2(Cf[mt][nt][0] + b0, Cf[mt][nt][1] + b1);
            float2 v1 = make_float2(Cf[mt][nt][2] + b0, Cf[mt][nt][3] + b1);
            if (MODE == 1) {
                *(float2*)(Cout + (size_t)row0 * DIMC + col) = v0;
                *(float2*)(Cout + (size_t)(row0 + 8) * DIMC + col) = v1;
            } else {
                int s = (col >= 2 * DIMC) ? 2 : (col >= DIMC ? 1 : 0);
                int rr = col - s * DIMC;
                int hh = rr / HD;
                int d = rr - hh * HD;
                int bb0 = row0 >> 11, t0 = row0 & (SEQ - 1);
                int r1 = row0 + 8;
                int bb1 = r1 >> 11, t1 = r1 & (SEQ - 1);
                if (s == 2) {
                    __half* dv0 = g_vth + ((size_t)(bb0 * NH + hh) * HD + d) * SEQ + t0;
                    dv0[0] = __float2half_rn(v0.x); dv0[SEQ] = __float2half_rn(v0.y);
                    __half* dv1 = g_vth + ((size_t)(bb1 * NH + hh) * HD + d) * SEQ + t1;
                    dv1[0] = __float2half_rn(v1.x); dv1[SEQ] = __float2half_rn(v1.y);
                } else {
                    float* base = (s == 0) ? g_q : g_k;
                    *(float2*)(base + ((size_t)(bb0 * NH + hh) * SEQ + t0) * HD + d) = v0;
                    *(float2*)(base + ((size_t)(bb1 * NH + hh) * SEQ + t1) * HD + d) = v1;
                }
            }
        }
    }
}

#define GEMM_SMEM_256 (3*(128+256)*KCH*2)
#define GEMM_SMEM_128 (3*(128+128)*KCH*2)

// ---------------------------------------------------------------------------
// RoPE: q in place (f32), k -> g_kh (fp16).
// ---------------------------------------------------------------------------
__global__ __launch_bounds__(256)
void rope_kernel()
{
    int idx = blockIdx.x * blockDim.x + threadIdx.x;
    int j = idx % 48;
    int rest = idx / 48;
    int t = rest & (SEQ - 1);
    int bh = rest >> 11;

    float freq = exp2f(-(2.f * j / 96.f) * 13.287712379549449f);
    float ang = (float)t * freq;
    float sn, cs;
    sincosf(ang, &sn, &cs);

    size_t base = ((size_t)bh * SEQ + t) * HD;
    float q1 = g_q[base + j], q2 = g_q[base + j + 48];
    g_q[base + j]      = q1 * cs - q2 * sn;
    g_q[base + j + 48] = q2 * cs + q1 * sn;
    float k1 = g_k[base + j], k2 = g_k[base + j + 48];
    g_kh[base + j]      = __float2half_rn(k1 * cs - k2 * sn);
    g_kh[base + j + 48] = __float2half_rn(k2 * cs + k1 * sn);
}

// ---------------------------------------------------------------------------
// Flash attention (R16 winner): fp16 mma, 2-stage ring, 2 CTAs/SM,
// log2-domain softmax with ex2.approx.f16x2, l via ones-row in V.
// ---------------------------------------------------------------------------
#define QLDH 104
#define KLDH 104
#define VTLDH 72
#define VROWS 112
#define KVSTGH (64*KLDH + VROWS*VTLDH)
#define ATTN_SMEM ((128*QLDH + 2*KVSTGH) * 2)

__global__ __launch_bounds__(256, 2)
void attn_mma()
{
    extern __shared__ __half smh[];
    __half* Qh = smh;
    __half* KV = smh + 128 * QLDH;

    int qt = gridDim.x - 1 - blockIdx.x;
    int hh = blockIdx.y, b = blockIdx.z;
    int tid = threadIdx.x;
    int lane = tid & 31;
    int wid = tid >> 5;
    int g = lane >> 2, j = lane & 3;
    const float scale = rsqrtf((float)HD) * 1.4426950408889634f;

    const float* Qg = g_q + ((size_t)(b * NH + hh) * SEQ + (size_t)qt * 128) * HD;
    const __half* Kg = g_kh + ((size_t)(b * NH + hh) * SEQ) * HD;
    const __half* Vtg = g_vth + ((size_t)(b * NH + hh) * HD) * SEQ;

    int nkt = 2 * qt + 2;

    auto issue_kv = [&](int kt) {
        int st = kt & 1;
        __half* Ks = KV + st * KVSTGH;
        __half* Vs = Ks + 64 * KLDH;
        const __half* kp = Kg + (size_t)kt * 64 * HD;
#pragma unroll
        for (int it = 0; it < 3; it++) {
            int f = tid + it * 256;
            int r = f / 12, ch = f % 12;
            cp16(smem_u32(Ks + r * KLDH + ch * 8), kp + (size_t)r * HD + ch * 8);
        }
        const __half* vp = Vtg + kt * 64;
#pragma unroll
        for (int it = 0; it < 3; it++) {
            int f = tid + it * 256;
            int d = f >> 3, ch = f & 7;
            cp16(smem_u32(Vs + d * VTLDH + ch * 8), vp + (size_t)d * SEQ + ch * 8);
        }
    };

    // constant V rows (96=ones, 97..111=zeros) in both stages
    for (int f = tid; f < 2 * 16 * VTLDH; f += 256) {
        int st = f / (16 * VTLDH);
        int rem = f - st * (16 * VTLDH);
        int r = 96 + rem / VTLDH;
        int c = rem % VTLDH;
        __half v = (r == 96) ? __float2half(1.f) : __float2half(0.f);
        (KV + st * KVSTGH + 64 * KLDH)[r * VTLDH + c] = v;
    }

    issue_kv(0); cp_commit();

    for (int f = tid; f < 128 * 24; f += 256) {
        int r = f / 24, c4 = (f % 24) * 4;
        float4 v = *(const float4*)(Qg + (size_t)r * HD + c4);
        uint32_t h0 = packh2(v.x * scale, v.y * scale);
        uint32_t h1 = packh2(v.z * scale, v.w * scale);
        uint32_t* dst = (uint32_t*)(Qh + r * QLDH + c4);
        dst[0] = h0; dst[1] = h1;
    }

    uint32_t qsb = smem_u32(Qh);
    uint32_t kvb = smem_u32(KV);
    int qRow = wid * 16 + (lane & 7) + ((lane >> 3) & 1) * 8;
    int qCol = ((lane >> 4) & 1) * 8;
    int bRow = (lane & 7) + ((lane >> 4) & 1) * 8;
    int bCol = ((lane >> 3) & 1) * 8;

    float m0r = -1e30f, m1r = -1e30f;
    float O[13][4];
#pragma unroll
    for (int nt = 0; nt < 13; nt++)
#pragma unroll
        for (int r = 0; r < 4; r++) O[nt][r] = 0.f;

    int row0 = qt * 128 + wid * 16 + g;

    for (int kt = 0; kt < nkt; kt++) {
        cp_wait0();
        __syncthreads();
        if (kt + 1 < nkt) issue_kv(kt + 1);
        cp_commit();

        uint32_t ksb = kvb + (uint32_t)((kt & 1) * KVSTGH) * 2;
        uint32_t vsb = ksb + (uint32_t)(64 * KLDH) * 2;

        float S[8][4];
#pragma unroll
        for (int nt = 0; nt < 8; nt++)
#pragma unroll
            for (int r = 0; r < 4; r++) S[nt][r] = 0.f;

#pragma unroll
        for (int ks = 0; ks < 6; ks++) {
            uint32_t a0, a1, a2, a3;
            ldsm4(a0, a1, a2, a3, qsb + (uint32_t)(qRow * QLDH + ks * 16 + qCol) * 2);
#pragma unroll
            for (int bk = 0; bk < 4; bk++) {
                uint32_t b0, b1, b2, b3;
                ldsm4(b0, b1, b2, b3,
                      ksb + (uint32_t)((bRow + bk * 16) * KLDH + ks * 16 + bCol) * 2);
                mma_h(S[2*bk],   a0, a1, a2, a3, b0, b1);
                mma_h(S[2*bk+1], a0, a1, a2, a3, b2, b3);
            }
        }

        if (kt >= nkt - 2) {
            int colb = kt * 64;
#pragma unroll
            for (int nt = 0; nt < 8; nt++) {
                int c0 = colb + nt * 8 + 2 * j;
                if (c0 > row0)     S[nt][0] = -1e30f;
                if (c0 + 1 > row0) S[nt][1] = -1e30f;
                if (c0 > row0 + 8)     S[nt][2] = -1e30f;
                if (c0 + 1 > row0 + 8) S[nt][3] = -1e30f;
            }
        }

        float mx0 = -1e30f, mx1 = -1e30f;
#pragma unroll
        for (int nt = 0; nt < 8; nt++) {
            mx0 = fmaxf(mx0, fmaxf(S[nt][0], S[nt][1]));
            mx1 = fmaxf(mx1, fmaxf(S[nt][2], S[nt][3]));
        }
        mx0 = fmaxf(mx0, __shfl_xor_sync(0xffffffffu, mx0, 1));
        mx0 = fmaxf(mx0, __shfl_xor_sync(0xffffffffu, mx0, 2));
        mx1 = fmaxf(mx1, __shfl_xor_sync(0xffffffffu, mx1, 1));
        mx1 = fmaxf(mx1, __shfl_xor_sync(0xffffffffu, mx1, 2));

        float mn0 = fmaxf(m0r, mx0), mn1 = fmaxf(m1r, mx1);
        float al0 = exp2f(m0r - mn0), al1 = exp2f(m1r - mn1);
        m0r = mn0; m1r = mn1;
#pragma unroll
        for (int nt = 0; nt < 13; nt++) {
            O[nt][0] *= al0; O[nt][1] *= al0;
            O[nt][2] *= al1; O[nt][3] *= al1;
        }

        uint32_t ph[8][2];
#pragma unroll
        for (int nt = 0; nt < 8; nt++) {
            ph[nt][0] = h2exp2(packh2(S[nt][0] - mn0, S[nt][1] - mn0));
            ph[nt][1] = h2exp2(packh2(S[nt][2] - mn1, S[nt][3] - mn1));
        }

#pragma unroll
        for (int ks = 0; ks < 4; ks++) {
            uint32_t a0 = ph[2*ks][0];
            uint32_t a1 = ph[2*ks][1];
            uint32_t a2 = ph[2*ks+1][0];
            uint32_t a3 = ph[2*ks+1][1];
#pragma unroll
            for (int bk = 0; bk < 7; bk++) {
                uint32_t b0, b1, b2, b3;
                ldsm4(b0, b1, b2, b3,
                      vsb + (uint32_t)((bRow + bk * 16) * VTLDH + ks * 16 + bCol) * 2);
                mma_h(O[2*bk], a0, a1, a2, a3, b0, b1);
                if (bk < 6) mma_h(O[2*bk+1], a0, a1, a2, a3, b2, b3);
            }
        }
    }

    float l0r = __shfl_sync(0xffffffffu, O[12][0], lane & ~3);
    float l1r = __shfl_sync(0xffffffffu, O[12][2], lane & ~3);
    float inv0 = 1.f / l0r, inv1 = 1.f / l1r;
    __half* outb = g_atth + ((size_t)b * SEQ + row0) * DIMC + hh * HD;
#pragma unroll
    for (int nt = 0; nt < 12; nt++) {
        int d = nt * 8 + 2 * j;
        *(uint32_t*)(outb + d) = packh2(O[nt][0] * inv0, O[nt][1] * inv0);
        *(uint32_t*)(outb + (size_t)8 * DIMC + d) = packh2(O[nt][2] * inv1, O[nt][3] * inv1);
    }
}

// ---------------------------------------------------------------------------
// Launch
// Inputs: 0=x, 1=mask (ignored, causal), 2=w_qkv, 3=b_qkv, 4=w_proj, 5=b_proj
// ---------------------------------------------------------------------------
extern "C" void kernel_launch(void* const* d_in, const int* in_sizes, int n_in,
                              void* d_out, int out_size)
{
    const float* x      = (const float*)d_in[0];
    const float* w_qkv  = (const float*)d_in[2];
    const float* b_qkv  = (const float*)d_in[3];
    const float* w_proj = (const float*)d_in[4];
    const float* b_proj = (const float*)d_in[5];
    float* out = (float*)d_out;

    cudaFuncSetAttribute(attn_mma, cudaFuncAttributeMaxDynamicSharedMemorySize,
                         ATTN_SMEM);
    cudaFuncSetAttribute((void*)gemm_h<0, 256, 2, 8>,
                         cudaFuncAttributeMaxDynamicSharedMemorySize, GEMM_SMEM_256);
    cudaFuncSetAttribute((void*)gemm_h<1, 128, 4, 4>,
                         cudaFuncAttributeMaxDynamicSharedMemorySize, GEMM_SMEM_128);

    __half *xh, *wqh, *wph, *ath;
    cudaGetSymbolAddress((void**)&xh,  g_xh);
    cudaGetSymbolAddress((void**)&wqh, g_wqh);
    cudaGetSymbolAddress((void**)&wph, g_wph);
    cudaGetSymbolAddress((void**)&ath, g_atth);

    // fused pack of all operands to fp16 (one launch)
    pack_all_kernel<<<(NX8 + NWQ8 + NWP8 + 255) / 256, 256>>>(x, w_qkv, w_proj);

    // QKV: M=8192, N=2304 (CTA tile 128x256, 512 threads)
    gemm_h<0, 256, 2, 8><<<dim3(2304 / 256, MTOT / 128), 512, GEMM_SMEM_256>>>(
        xh, wqh, b_qkv, nullptr);

    // RoPE (q f32 in place, k -> fp16)
    rope_kernel<<<(BATCH * NH * SEQ * 48) / 256, 256>>>();

    // Attention (fp16, 2-stage ring, 2 CTAs/SM, ex2.approx softmax)
    attn_mma<<<dim3(SEQ / 128, NH, BATCH), 256, ATTN_SMEM>>>();

    // Projection: M=8192, N=768 (CTA tile 128x128, 512 threads)
    gemm_h<1, 128, 4, 4><<<dim3(DIMC / 128, MTOT / 128), 512, GEMM_SMEM_128>>>(
        ath, wph, b_proj, out);
}